// round 1
// baseline (speedup 1.0000x reference)
#include <cuda_runtime.h>
#include <cuda_bf16.h>

#define KK   27
#define CIN  16
#define COUT 16
#define TPB  256
#define NPT  2          // nodes per thread
#define NODES_PER_BLOCK (TPB * NPT)

// ---- packed f32x2 helpers (sm_100+ FFMA2 path, 2x fp32 FMA throughput) ----

__device__ __forceinline__ unsigned long long splat2(float v) {
    unsigned long long r;
    asm("mov.b64 %0, {%1, %1};" : "=l"(r) : "f"(v));
    return r;
}

__device__ __forceinline__ unsigned long long pack2(float lo, float hi) {
    unsigned long long r;
    asm("mov.b64 %0, {%1, %2};" : "=l"(r) : "f"(lo), "f"(hi));
    return r;
}

__device__ __forceinline__ void ffma2(unsigned long long& d,
                                      unsigned long long a,
                                      unsigned long long b) {
    // d = a * b + d, lanewise on two packed fp32
    asm("fma.rn.f32x2 %0, %1, %2, %0;" : "+l"(d) : "l"(a), "l"(b));
}

// ---- main conv kernel ----
// Y[i][o] = bias[o] + sum_k sum_c X[nbr[i][k]][c] * W[k][c][o]

__global__ __launch_bounds__(TPB, 2)
void conv_kernel(const float* __restrict__ x,       // [N_in, 16]
                 const float* __restrict__ w,       // [27, 16, 16]
                 const float* __restrict__ bias,    // [16]
                 const int*   __restrict__ nbr,     // [N_out, 27]
                 float*       __restrict__ out,     // [N_out, 16]
                 int n_out)
{
    __shared__ __align__(16) float ws[KK * CIN * COUT];   // 27648 B
    __shared__ float bs[COUT];

    for (int i = threadIdx.x; i < KK * CIN * COUT; i += TPB) ws[i] = w[i];
    if (threadIdx.x < COUT) bs[threadIdx.x] = bias[threadIdx.x];
    __syncthreads();

    const int n0 = blockIdx.x * NODES_PER_BLOCK + threadIdx.x * NPT;
    const int n1 = n0 + 1;
    if (n0 >= n_out) return;
    const bool v1 = (n1 < n_out);

    // accumulators: 8 packed pairs per node, init to bias
    unsigned long long acc0[8], acc1[8];
#pragma unroll
    for (int p = 0; p < 8; ++p) {
        acc0[p] = pack2(bs[2 * p], bs[2 * p + 1]);
        acc1[p] = acc0[p];
    }

    const int* nb0 = nbr + (size_t)n0 * KK;
    const int* nb1 = nbr + (size_t)(v1 ? n1 : n0) * KK;

#pragma unroll 1
    for (int k = 0; k < KK; ++k) {
        const int j0 = __ldg(&nb0[k]);
        const int j1 = __ldg(&nb1[k]);

        // gather two input rows (64 B each) — random, L2-resident
        const float4* r0 = reinterpret_cast<const float4*>(x + (size_t)j0 * CIN);
        const float4* r1 = reinterpret_cast<const float4*>(x + (size_t)j1 * CIN);
        float4 a0 = __ldg(&r0[0]), a1 = __ldg(&r0[1]),
               a2 = __ldg(&r0[2]), a3 = __ldg(&r0[3]);
        float4 b0 = __ldg(&r1[0]), b1 = __ldg(&r1[1]),
               b2 = __ldg(&r1[2]), b3 = __ldg(&r1[3]);

        float xa0[16] = {a0.x, a0.y, a0.z, a0.w, a1.x, a1.y, a1.z, a1.w,
                         a2.x, a2.y, a2.z, a2.w, a3.x, a3.y, a3.z, a3.w};
        float xa1[16] = {b0.x, b0.y, b0.z, b0.w, b1.x, b1.y, b1.z, b1.w,
                         b2.x, b2.y, b2.z, b2.w, b3.x, b3.y, b3.z, b3.w};

        const float* wk = ws + k * (CIN * COUT);
#pragma unroll
        for (int c = 0; c < CIN; ++c) {
            const unsigned long long xp0 = splat2(xa0[c]);
            const unsigned long long xp1 = splat2(xa1[c]);
            const ulonglong2* wc =
                reinterpret_cast<const ulonglong2*>(wk + c * COUT);
#pragma unroll
            for (int q = 0; q < 4; ++q) {
                ulonglong2 wp = wc[q];      // 4 weights, LDS.128 broadcast
                ffma2(acc0[2 * q],     xp0, wp.x);
                ffma2(acc0[2 * q + 1], xp0, wp.y);
                ffma2(acc1[2 * q],     xp1, wp.x);
                ffma2(acc1[2 * q + 1], xp1, wp.y);
            }
        }
    }

    // store: 4x STG.128 per node
    {
        ulonglong2* o0 = reinterpret_cast<ulonglong2*>(out + (size_t)n0 * COUT);
#pragma unroll
        for (int q = 0; q < 4; ++q) {
            ulonglong2 t; t.x = acc0[2 * q]; t.y = acc0[2 * q + 1];
            o0[q] = t;
        }
    }
    if (v1) {
        ulonglong2* o1 = reinterpret_cast<ulonglong2*>(out + (size_t)n1 * COUT);
#pragma unroll
        for (int q = 0; q < 4; ++q) {
            ulonglong2 t; t.x = acc1[2 * q]; t.y = acc1[2 * q + 1];
            o1[q] = t;
        }
    }
}

// level passthrough for any trailing output elements beyond N_out*16
__global__ void tail_kernel(const int* __restrict__ level,
                            float* __restrict__ out,
                            long long start, long long count)
{
    long long i = (long long)blockIdx.x * blockDim.x + threadIdx.x;
    if (i < count) out[start + i] = (float)(*level);
}

extern "C" void kernel_launch(void* const* d_in, const int* in_sizes, int n_in,
                              void* d_out, int out_size)
{
    const float* x    = (const float*)d_in[0];
    const float* w    = (const float*)d_in[1];
    const float* bias = (const float*)d_in[2];
    const int*   nbr  = (const int*)d_in[3];
    const int*   lvl  = (n_in > 4) ? (const int*)d_in[4] : nullptr;

    const int n_out = in_sizes[3] / KK;
    float* out = (float*)d_out;

    const int grid = (n_out + NODES_PER_BLOCK - 1) / NODES_PER_BLOCK;
    conv_kernel<<<grid, TPB>>>(x, w, bias, nbr, out, n_out);

    const long long conv_elems = (long long)n_out * COUT;
    if ((long long)out_size > conv_elems && lvl != nullptr) {
        long long rem = (long long)out_size - conv_elems;
        int tgrid = (int)((rem + 127) / 128);
        tail_kernel<<<tgrid, 128>>>(lvl, out, conv_elems, rem);
    }
}